// round 13
// baseline (speedup 1.0000x reference)
#include <cuda_runtime.h>
#include <cuda_fp16.h>
#include <math_constants.h>
#include <cstdint>

#define BS 128
#define M_CTR 16
#define BN_SCALE 0.9999950000374997f

// ---------------- scratch ----------------
__device__ int    g_fps[BS * M_CTR];
__device__ int    g_knn[BS * M_CTR * 2];
__device__ float  g_GsT[65536 * 128];            // dense C [n=b*512+s*16+p][o]
__device__ __half g_d4h[BS * 16 * 32 * 128];     // d4 (half) [b][m][x][i]

// ---------------- helpers ----------------
__device__ __forceinline__ float gelu_exact(float x) {
    return 0.5f * x * (1.0f + erff(x * 0.70710678118654752f));
}
__device__ __forceinline__ float bn_gelu(float x, float g, float beta) {
    return gelu_exact(fmaf(g, x * BN_SCALE, beta));
}
__device__ __forceinline__ uint32_t pack_h2(float lo, float hi) {
    __half2 h = __floats2half2_rn(lo, hi);
    return *reinterpret_cast<uint32_t*>(&h);
}
__device__ __forceinline__ void mma_f16(float* d, const uint32_t* a, const uint32_t* b) {
    asm volatile(
        "mma.sync.aligned.m16n8k16.row.col.f32.f16.f16.f32 "
        "{%0,%1,%2,%3}, {%4,%5,%6,%7}, {%8,%9}, {%0,%1,%2,%3};\n"
        : "+f"(d[0]), "+f"(d[1]), "+f"(d[2]), "+f"(d[3])
        : "r"(a[0]), "r"(a[1]), "r"(a[2]), "r"(a[3]), "r"(b[0]), "r"(b[1]));
}

// ---------------------------------------------------------------------------
// FPS + kNN + coor_out.  One warp per batch. (exact f32, matches reference)
// ---------------------------------------------------------------------------
__global__ __launch_bounds__(32) void k_fps_knn(const float* __restrict__ coor,
                                                float* __restrict__ coor_out) {
    int b = blockIdx.x;
    int t = threadIdx.x;
    __shared__ float cs[32][33];
    __shared__ float sq[32];
    __shared__ int   fpsi[M_CTR];

    for (int c = 0; c < 32; c++) cs[t][c] = coor[(b * 32 + t) * 32 + c];
    float s = 0.f;
    for (int c = 0; c < 32; c++) { float v = cs[t][c]; s += v * v; }
    sq[t] = s;
    __syncthreads();

    float dist = CUDART_INF_F;
    int far = 0;
    for (int it = 0; it < M_CTR; it++) {
        if (t == 0) fpsi[it] = far;
        float d = 0.f;
        #pragma unroll
        for (int c = 0; c < 32; c++) { float df = cs[t][c] - cs[far][c]; d += df * df; }
        dist = fminf(dist, d);
        float bv = dist; int bi = t;
        #pragma unroll
        for (int o = 16; o > 0; o >>= 1) {
            float ov = __shfl_xor_sync(0xffffffffu, bv, o);
            int   oi = __shfl_xor_sync(0xffffffffu, bi, o);
            if (ov > bv || (ov == bv && oi < bi)) { bv = ov; bi = oi; }
        }
        far = bi;
    }
    __syncthreads();

    for (int m = 0; m < M_CTR; m++) {
        int r = fpsi[m];
        coor_out[(b * M_CTR + m) * 32 + t] = cs[r][t];
    }
    for (int m = 0; m < M_CTR; m++) {
        int ctr = fpsi[m];
        float dot = 0.f;
        #pragma unroll
        for (int c = 0; c < 32; c++) dot += cs[ctr][c] * cs[t][c];
        float d = sq[ctr] + sq[t] - 2.0f * dot;
        float bv = d; int bi = t;
        #pragma unroll
        for (int o = 16; o > 0; o >>= 1) {
            float ov = __shfl_xor_sync(0xffffffffu, bv, o);
            int   oi = __shfl_xor_sync(0xffffffffu, bi, o);
            if (ov < bv || (ov == bv && oi < bi)) { bv = ov; bi = oi; }
        }
        int i1 = bi;
        float d2 = (t == i1) ? CUDART_INF_F : d;
        float cv = d2; int ci = t;
        #pragma unroll
        for (int o = 16; o > 0; o >>= 1) {
            float ov = __shfl_xor_sync(0xffffffffu, cv, o);
            int   oi = __shfl_xor_sync(0xffffffffu, ci, o);
            if (ov < cv || (ov == cv && oi < ci)) { cv = ov; ci = oi; }
        }
        if (t == 0) {
            g_knn[(b * M_CTR + m) * 2 + 0] = i1;
            g_knn[(b * M_CTR + m) * 2 + 1] = ci;
        }
    }
    if (t < M_CTR) g_fps[b * M_CTR + t] = fpsi[t];
}

// ---------------------------------------------------------------------------
// FAT kernel: blocks [0,256) = sparse GEMM+epilogue; [256,768) = dense GEMM.
// Both fp16 MMA, KC=32, fragment-order half2 smem (dynamic, 67584B).
// (frozen — validated at 104.6us)
// ---------------------------------------------------------------------------
__global__ __launch_bounds__(256, 2) void fat_gemm(
        const float* __restrict__ sp_w, const float* __restrict__ sparse_fea,
        const float* __restrict__ sp_b, const float* __restrict__ sp_g,
        const float* __restrict__ sp_beta, float* __restrict__ out_sparse,
        const float* __restrict__ dn_w, const float* __restrict__ dense_fea) {
    extern __shared__ uint32_t dsm[];

    const int t = threadIdx.x;
    const int lane = t & 31;
    const int wid = t >> 5;
    const int g = lane >> 2, t4 = lane & 3;

    if (blockIdx.x < 256) {
        // =================== SPARSE PATH (128x64 tile) =====================
        uint32_t* SA = dsm;            // [2][2048]
        uint32_t* SB = dsm + 4096;     // [2][1024]
        float*    Cs = reinterpret_cast<float*>(dsm);   // [128][65]

        const int wm = wid & 3, wn = wid >> 2;
        int b0 = (blockIdx.x & 63) * 2;
        int oT = (blockIdx.x >> 6) * 64;

        float2 ra2[8];
        float rb[8];

        auto loadA = [&](int ch) {
            int k0 = ch * 32;
            #pragma unroll
            for (int j = 0; j < 8; j++) {
                int idx = j * 256 + t;
                int kp = idx & 15, m = idx >> 4;
                int o = oT + (m & 63);
                ra2[j] = *reinterpret_cast<const float2*>(
                    &sp_w[(size_t)o * 512 + ((m < 64) ? 0 : 256) + k0 + 2 * kp]);
            }
        };
        auto loadB = [&](int ch) {
            int k0 = ch * 32;
            #pragma unroll
            for (int j = 0; j < 4; j++) {
                int idx = j * 256 + t;
                int n = idx & 63, kp = idx >> 6;
                int b = b0 + (n >> 5), s = n & 31;
                rb[2 * j]     = __ldg(&sparse_fea[((size_t)b * 256 + k0 + 2 * kp) * 32 + s]);
                rb[2 * j + 1] = __ldg(&sparse_fea[((size_t)b * 256 + k0 + 2 * kp + 1) * 32 + s]);
            }
        };
        auto storeA = [&](int buf) {
            #pragma unroll
            for (int j = 0; j < 8; j++) {
                int idx = j * 256 + t;
                int kp = idx & 15, m = idx >> 4;
                int tile = m >> 4, r = m & 15;
                int ks = kp >> 3, kpl = kp & 7;
                int ln = (r & 7) * 4 + (kpl & 3);
                int slot = (r >> 3) + 2 * (kpl >> 2);
                SA[buf * 2048 + ((tile * 2 + ks) << 7) + (ln << 2) + slot] =
                    pack_h2(ra2[j].x, ra2[j].y);
            }
        };
        auto storeB = [&](int buf) {
            #pragma unroll
            for (int j = 0; j < 4; j++) {
                int idx = j * 256 + t;
                int n = idx & 63, kp = idx >> 6;
                int ks = kp >> 3, kpl = kp & 7;
                int ntile = n >> 3;
                int ln = (n & 7) * 4 + (kpl & 3);
                int slot = kpl >> 2;
                SB[buf * 1024 + ((ntile * 2 + ks) << 6) + (ln << 1) + slot] =
                    pack_h2(rb[2 * j], rb[2 * j + 1]);
            }
        };

        float d[2][4][4];
        #pragma unroll
        for (int mt = 0; mt < 2; mt++)
            #pragma unroll
            for (int nt = 0; nt < 4; nt++)
                #pragma unroll
                for (int e = 0; e < 4; e++) d[mt][nt][e] = 0.f;

        loadA(0); loadB(0);
        storeA(0); storeB(0);
        __syncthreads();

        for (int ch = 0; ch < 8; ch++) {
            int buf = ch & 1;
            if (ch + 1 < 8) { loadA(ch + 1); loadB(ch + 1); }
            const uint4* Af = reinterpret_cast<const uint4*>(SA + buf * 2048);
            const uint2* Bf = reinterpret_cast<const uint2*>(SB + buf * 1024);
            #pragma unroll
            for (int ks = 0; ks < 2; ks++) {
                uint32_t a[2][4], bfr[4][2];
                #pragma unroll
                for (int mt = 0; mt < 2; mt++) {
                    uint4 av = Af[((2 * wm + mt) * 2 + ks) * 32 + lane];
                    a[mt][0] = av.x; a[mt][1] = av.y; a[mt][2] = av.z; a[mt][3] = av.w;
                }
                #pragma unroll
                for (int nt = 0; nt < 4; nt++) {
                    uint2 bv = Bf[((wn * 4 + nt) * 2 + ks) * 32 + lane];
                    bfr[nt][0] = bv.x; bfr[nt][1] = bv.y;
                }
                #pragma unroll
                for (int mt = 0; mt < 2; mt++)
                    #pragma unroll
                    for (int nt = 0; nt < 4; nt++)
                        mma_f16(d[mt][nt], a[mt], bfr[nt]);
            }
            if (ch + 1 < 8) { storeA(1 - buf); storeB(1 - buf); }
            __syncthreads();
        }

        #pragma unroll
        for (int mt = 0; mt < 2; mt++)
            #pragma unroll
            for (int nt = 0; nt < 4; nt++)
                #pragma unroll
                for (int e = 0; e < 4; e++) {
                    int m = wm * 32 + mt * 16 + g + ((e & 2) ? 8 : 0);
                    int n = wn * 32 + nt * 8 + 2 * t4 + (e & 1);
                    Cs[m * 65 + n] = d[mt][nt][e];
                }
        __syncthreads();
        #pragma unroll
        for (int j = 0; j < 8; j++) {
            int idx = j * 256 + t;
            int mm = idx & 15;
            int o_loc = (idx >> 4) & 63;
            int bl = idx >> 10;
            int b = b0 + bl;
            int cb = bl * 32;
            int ctr = g_fps[b * M_CTR + mm];
            int i0 = g_knn[(b * M_CTR + mm) * 2 + 0];
            int i1 = g_knn[(b * M_CTR + mm) * 2 + 1];
            float Ha_c = Cs[o_loc * 65 + cb + ctr];
            float Hc_c = Cs[(64 + o_loc) * 65 + cb + ctr];
            float Ha0  = Cs[o_loc * 65 + cb + i0];
            float Ha1  = Cs[o_loc * 65 + cb + i1];
            int o = oT + o_loc;
            float base = -Ha_c + Hc_c + sp_b[o];
            float gg = sp_g[o], bt = sp_beta[o];
            float r = fmaxf(bn_gelu(Ha0 + base, gg, bt), bn_gelu(Ha1 + base, gg, bt));
            out_sparse[(size_t)b * 4096 + o * 16 + mm] = r;
        }
    } else {
        // =================== DENSE PATH (128x128 tile) =====================
        uint32_t* Abuf = dsm;          // [2][2048]
        uint32_t* Bbuf = dsm + 4096;   // [2][2048]
        float*    Cs   = reinterpret_cast<float*>(dsm);   // [n][132]

        const int wm = wid & 1, wn = wid >> 1;
        int dx = blockIdx.x - 256;
        int bb = dx >> 2, sg = dx & 3, s0 = sg * 8;

        uint32_t rap[8], rbp[8];

        auto loadA = [&](int ch) {
            int k0 = ch * 32;
            #pragma unroll
            for (int j = 0; j < 8; j++) {
                int idx = j * 256 + t;
                int kp = idx & 15, m = idx >> 4;
                int cc = (k0 >> 1) + kp;
                float x = __ldg(&dn_w[m * 256 + cc]);
                float y = __ldg(&dn_w[m * 256 + 128 + cc]);
                rap[j] = pack_h2(x, y);
            }
        };
        auto loadB = [&](int ch) {
            int k0 = ch * 32;
            #pragma unroll
            for (int j = 0; j < 8; j++) {
                int idx = j * 256 + t;
                int n = idx & 127, kp = idx >> 7;
                int c = (k0 >> 1) + kp;
                int s = s0 + (n >> 4), p = n & 15;
                float2 v = *reinterpret_cast<const float2*>(
                    &dense_fea[(((size_t)bb * 128 + c) * 32 + s) * 32 + 2 * p]);
                rbp[j] = pack_h2(v.x, v.y);
            }
        };
        auto storeA = [&](int buf) {
            #pragma unroll
            for (int j = 0; j < 8; j++) {
                int idx = j * 256 + t;
                int kp = idx & 15, m = idx >> 4;
                int tile = m >> 4, r = m & 15;
                int ks = kp >> 3, kpl = kp & 7;
                int ln = (r & 7) * 4 + (kpl & 3);
                int slot = (r >> 3) + 2 * (kpl >> 2);
                Abuf[buf * 2048 + ((tile * 2 + ks) << 7) + (ln << 2) + slot] = rap[j];
            }
        };
        auto storeB = [&](int buf) {
            #pragma unroll
            for (int j = 0; j < 8; j++) {
                int idx = j * 256 + t;
                int n = idx & 127, kp = idx >> 7;
                int ks = kp >> 3, kpl = kp & 7;
                int ntile = n >> 3;
                int ln = (n & 7) * 4 + (kpl & 3);
                int slot = kpl >> 2;
                Bbuf[buf * 2048 + ((ntile * 2 + ks) << 6) + (ln << 1) + slot] = rbp[j];
            }
        };

        float d[4][4][4];
        #pragma unroll
        for (int mt = 0; mt < 4; mt++)
            #pragma unroll
            for (int nt = 0; nt < 4; nt++)
                #pragma unroll
                for (int e = 0; e < 4; e++) d[mt][nt][e] = 0.f;

        loadA(0); loadB(0);
        storeA(0); storeB(0);
        __syncthreads();

        for (int ch = 0; ch < 8; ch++) {
            int buf = ch & 1;
            if (ch + 1 < 8) { loadA(ch + 1); loadB(ch + 1); }
            const uint4* Af = reinterpret_cast<const uint4*>(Abuf + buf * 2048);
            const uint2* Bf = reinterpret_cast<const uint2*>(Bbuf + buf * 2048);
            #pragma unroll
            for (int ks = 0; ks < 2; ks++) {
                uint32_t a[4][4], bfr[4][2];
                #pragma unroll
                for (int mt = 0; mt < 4; mt++) {
                    uint4 av = Af[((wm * 4 + mt) * 2 + ks) * 32 + lane];
                    a[mt][0] = av.x; a[mt][1] = av.y; a[mt][2] = av.z; a[mt][3] = av.w;
                }
                #pragma unroll
                for (int nt = 0; nt < 4; nt++) {
                    uint2 bv = Bf[((wn * 4 + nt) * 2 + ks) * 32 + lane];
                    bfr[nt][0] = bv.x; bfr[nt][1] = bv.y;
                }
                #pragma unroll
                for (int mt = 0; mt < 4; mt++)
                    #pragma unroll
                    for (int nt = 0; nt < 4; nt++)
                        mma_f16(d[mt][nt], a[mt], bfr[nt]);
            }
            if (ch + 1 < 8) { storeA(1 - buf); storeB(1 - buf); }
            __syncthreads();
        }

        // transpose through smem: Cs[n][m] stride 132 -> float4 stores
        #pragma unroll
        for (int mt = 0; mt < 4; mt++)
            #pragma unroll
            for (int nt = 0; nt < 4; nt++)
                #pragma unroll
                for (int e = 0; e < 4; e++) {
                    int m = wm * 64 + mt * 16 + g + ((e & 2) ? 8 : 0);
                    int n = wn * 32 + nt * 8 + 2 * t4 + (e & 1);
                    Cs[n * 132 + m] = d[mt][nt][e];
                }
        __syncthreads();
        #pragma unroll
        for (int j = 0; j < 16; j++) {
            int idx = j * 256 + t;
            int o4 = (idx & 31) * 4, n = idx >> 5;
            float4 v = *reinterpret_cast<const float4*>(&Cs[n * 132 + o4]);
            *reinterpret_cast<float4*>(
                &g_GsT[((size_t)bb * 512 + sg * 128 + n) * 128 + o4]) = v;
        }
    }
}

// ---------------------------------------------------------------------------
// d4 paired-p, writes HALF (pre-packed for conv B-fill)
// ---------------------------------------------------------------------------
__global__ __launch_bounds__(256) void k_d4(const float* __restrict__ dn_b,
                                            const float* __restrict__ dn_g,
                                            const float* __restrict__ dn_beta) {
    int tid = blockIdx.x * 256 + threadIdx.x;
    int i = (tid & 31) * 4;
    int p = (tid >> 5) & 15;
    int m = (tid >> 9) & 15;
    int b = tid >> 13;
    int ctr = g_fps[b * M_CTR + m];
    int i0 = g_knn[(b * M_CTR + m) * 2 + 0];
    int i1 = g_knn[(b * M_CTR + m) * 2 + 1];
    float4 bb = *reinterpret_cast<const float4*>(&dn_b[i]);
    float4 gg = *reinterpret_cast<const float4*>(&dn_g[i]);
    float4 bt = *reinterpret_cast<const float4*>(&dn_beta[i]);
    const float* Gb = g_GsT + (size_t)b * 512 * 128;
    float4 gc = *reinterpret_cast<const float4*>(&Gb[(size_t)(ctr * 16 + p) * 128 + i]);
    float4 x0 = *reinterpret_cast<const float4*>(&Gb[(size_t)(i0 * 16 + p) * 128 + i]);
    float4 x1 = *reinterpret_cast<const float4*>(&Gb[(size_t)(i1 * 16 + p) * 128 + i]);
    float4 va, vb2;
    va.x = fmaxf(bn_gelu(x0.x - gc.x + bb.x, gg.x, bt.x), bn_gelu(x1.x - gc.x + bb.x, gg.x, bt.x));
    va.y = fmaxf(bn_gelu(x0.y - gc.y + bb.y, gg.y, bt.y), bn_gelu(x1.y - gc.y + bb.y, gg.y, bt.y));
    va.z = fmaxf(bn_gelu(x0.z - gc.z + bb.z, gg.z, bt.z), bn_gelu(x1.z - gc.z + bb.z, gg.z, bt.z));
    va.w = fmaxf(bn_gelu(x0.w - gc.w + bb.w, gg.w, bt.w), bn_gelu(x1.w - gc.w + bb.w, gg.w, bt.w));
    vb2.x = bn_gelu(gc.x + bb.x, gg.x, bt.x);
    vb2.y = bn_gelu(gc.y + bb.y, gg.y, bt.y);
    vb2.z = bn_gelu(gc.z + bb.z, gg.z, bt.z);
    vb2.w = bn_gelu(gc.w + bb.w, gg.w, bt.w);
    __half* outp = g_d4h + (((size_t)b * 16 + m) * 32 + p) * 128 + i;
    uint2 pa = make_uint2(pack_h2(va.x, va.y), pack_h2(va.z, va.w));
    uint2 pb = make_uint2(pack_h2(vb2.x, vb2.y), pack_h2(vb2.z, vb2.w));
    *reinterpret_cast<uint2*>(outp) = pa;
    *reinterpret_cast<uint2*>(outp + 16 * 128) = pb;
}

// ---------------------------------------------------------------------------
// Conv GEMM: 128x64 tile (sparse-path geometry: 8 warps 4Mx2N, warp 32x32),
// KC=32, fp16 MMA, coalesced kq-major B-fill from half g_d4h.
// grid 512 (bb x 4 n-tiles), 3 CTAs/SM target.
// ---------------------------------------------------------------------------
__global__ __launch_bounds__(256, 3) void gemm_conv(const float* __restrict__ A0,
                                                    const float* __restrict__ eb,
                                                    const float* __restrict__ eg,
                                                    const float* __restrict__ ebt,
                                                    float* __restrict__ Cout) {
    extern __shared__ uint32_t dsm[];
    uint32_t* Abuf = dsm;          // [2][2048]
    uint32_t* Bbuf = dsm + 4096;   // [2][1024]

    const int t = threadIdx.x;
    const int lane = t & 31;
    const int wid = t >> 5;
    const int g = lane >> 2, t4 = lane & 3;
    const int wm = wid & 3, wn = wid >> 2;

    int bb = blockIdx.x >> 2, ng = blockIdx.x & 3;

    const int NCH = 12;
    uint32_t rap[8], rbp[4];

    auto loadA = [&](int ch) {
        int k0 = ch * 32;
        int tap = k0 >> 7, i0 = k0 & 127;
        #pragma unroll
        for (int j = 0; j < 8; j++) {
            int idx = j * 256 + t;
            int kp = idx & 15, m = idx >> 4;
            int i = i0 + 2 * kp;
            float x = __ldg(&A0[m * 384 + i * 3 + tap]);
            float y = __ldg(&A0[m * 384 + (i + 1) * 3 + tap]);
            rap[j] = pack_h2(x, y);
        }
    };
    auto loadB = [&](int ch) {
        int k0 = ch * 32;
        int tap = k0 >> 7, i0 = k0 & 127;
        #pragma unroll
        for (int j = 0; j < 2; j++) {
            int idx = j * 256 + t;            // 0..511
            int kq = idx & 7;                 // kp pair: 2*kq, 2*kq+1
            int n = idx >> 3;                 // 0..63
            int i = i0 + 4 * kq;
            int ngl = ng * 64 + n;
            int m = ngl >> 4, w = ngl & 15;
            int x = 2 * w - 1 + tap;
            uint2 v = (x >= 0 && x < 32)
                ? *reinterpret_cast<const uint2*>(
                      &g_d4h[(((size_t)bb * 16 + m) * 32 + x) * 128 + i])
                : make_uint2(0u, 0u);
            rbp[2 * j]     = v.x;
            rbp[2 * j + 1] = v.y;
        }
    };
    auto storeA = [&](int buf) {
        #pragma unroll
        for (int j = 0; j < 8; j++) {
            int idx = j * 256 + t;
            int kp = idx & 15, m = idx >> 4;
            int tile = m >> 4, r = m & 15;
            int ks = kp >> 3, kpl = kp & 7;
            int ln = (r & 7) * 4 + (kpl & 3);
            int slot = (r >> 3) + 2 * (kpl >> 2);
            Abuf[buf * 2048 + ((tile * 2 + ks) << 7) + (ln << 2) + slot] = rap[j];
        }
    };
    auto storeB = [&](int buf) {
        #pragma unroll
        for (int j = 0; j < 2; j++) {
            int idx = j * 256 + t;
            int kq = idx & 7;
            int n = idx >> 3;
            #pragma unroll
            for (int h = 0; h < 2; h++) {
                int kp = 2 * kq + h;
                int ks = kp >> 3, kpl = kp & 7;
                int ntile = n >> 3;
                int ln = (n & 7) * 4 + (kpl & 3);
                int slot = kpl >> 2;
                Bbuf[buf * 1024 + ((ntile * 2 + ks) << 6) + (ln << 1) + slot] =
                    rbp[2 * j + h];
            }
        }
    };

    float d[2][4][4];
    #pragma unroll
    for (int mt = 0; mt < 2; mt++)
        #pragma unroll
        for (int nt = 0; nt < 4; nt++)
            #pragma unroll
            for (int e = 0; e < 4; e++) d[mt][nt][e] = 0.f;

    loadA(0); loadB(0);
    storeA(0); storeB(0);
    __syncthreads();

    for (int ch = 0; ch < NCH; ch++) {
        int buf = ch & 1;
        if (ch + 1 < NCH) { loadA(ch + 1); loadB(ch + 1); }
        const uint4* Af = reinterpret_cast<const uint4*>(Abuf + buf * 2048);
        const uint2* Bf = reinterpret_cast<const uint2*>(Bbuf + buf * 1024);
        #pragma unroll
        for (int ks = 0; ks < 2; ks++) {
            uint32_t a[2][4], bfr[4][2];
            #pragma unroll
            for (int mt = 0; mt < 2; mt++) {
                uint4 av = Af[((2 * wm + mt) * 2 + ks) * 32 + lane];
                a[mt][0] = av.x; a[mt][1] = av.y; a[mt][2] = av.z; a[mt][3] = av.w;
            }
            #pragma unroll
            for (int nt = 0; nt < 4; nt++) {
                uint2 bv = Bf[((wn * 4 + nt) * 2 + ks) * 32 + lane];
                bfr[nt][0] = bv.x; bfr[nt][1] = bv.y;
            }
            #pragma unroll
            for (int mt = 0; mt < 2; mt++)
                #pragma unroll
                for (int nt = 0; nt < 4; nt++)
                    mma_f16(d[mt][nt], a[mt], bfr[nt]);
        }
        if (ch + 1 < NCH) { storeA(1 - buf); storeB(1 - buf); }
        __syncthreads();
    }

    #pragma unroll
    for (int mt = 0; mt < 2; mt++) {
        int o_lo = wm * 32 + mt * 16 + g;
        int o_hi = o_lo + 8;
        float b_lo = eb[o_lo], g_lo = eg[o_lo], t_lo = ebt[o_lo];
        float b_hi = eb[o_hi], g_hi = eg[o_hi], t_hi = ebt[o_hi];
        #pragma unroll
        for (int nt = 0; nt < 4; nt++) {
            int n = ng * 64 + wn * 32 + nt * 8 + 2 * t4;
            float2 v0, v1;
            v0.x = bn_gelu(d[mt][nt][0] + b_lo, g_lo, t_lo);
            v0.y = bn_gelu(d[mt][nt][1] + b_lo, g_lo, t_lo);
            v1.x = bn_gelu(d[mt][nt][2] + b_hi, g_hi, t_hi);
            v1.y = bn_gelu(d[mt][nt][3] + b_hi, g_hi, t_hi);
            *reinterpret_cast<float2*>(&Cout[((size_t)bb * 128 + o_lo) * 256 + n]) = v0;
            *reinterpret_cast<float2*>(&Cout[((size_t)bb * 128 + o_hi) * 256 + n]) = v1;
        }
    }
}

// ---------------------------------------------------------------------------
extern "C" void kernel_launch(void* const* d_in, const int* in_sizes, int n_in,
                              void* d_out, int out_size) {
    const float* sparse_fea = (const float*)d_in[0];
    const float* dense_fea  = (const float*)d_in[1];
    const float* stk_coor   = (const float*)d_in[2];
    int base = 3;
    if (n_in >= 16 && in_sizes[3] == 1) base = 4;
    const float* sp_w    = (const float*)d_in[base + 0];
    const float* sp_b    = (const float*)d_in[base + 1];
    const float* sp_g    = (const float*)d_in[base + 2];
    const float* sp_beta = (const float*)d_in[base + 3];
    const float* dn_w    = (const float*)d_in[base + 4];
    const float* dn_b    = (const float*)d_in[base + 5];
    const float* dn_g    = (const float*)d_in[base + 6];
    const float* dn_beta = (const float*)d_in[base + 7];
    const float* ds_w    = (const float*)d_in[base + 8];
    const float* ds_b    = (const float*)d_in[base + 9];
    const float* ds_g    = (const float*)d_in[base + 10];
    const float* ds_beta = (const float*)d_in[base + 11];

    float* out = (float*)d_out;
    float* out_sparse = out;
    float* out_dense  = out + BS * 256 * M_CTR;
    float* out_coor   = out_dense + BS * 128 * M_CTR * 16;

    static bool attr_done = false;
    if (!attr_done) {
        cudaFuncSetAttribute(fat_gemm, cudaFuncAttributeMaxDynamicSharedMemorySize, 69632);
        attr_done = true;
    }

    k_fps_knn<<<BS, 32>>>(stk_coor, out_coor);
    fat_gemm<<<768, 256, 67584>>>(sp_w, sparse_fea, sp_b, sp_g, sp_beta, out_sparse,
                                  dn_w, dense_fea);
    k_d4<<<4096, 256>>>(dn_b, dn_g, dn_beta);
    gemm_conv<<<512, 256, 24576>>>(ds_w, ds_b, ds_g, ds_beta, out_dense);
}

// round 14
// speedup vs baseline: 1.1841x; 1.1841x over previous
#include <cuda_runtime.h>
#include <cuda_fp16.h>
#include <math_constants.h>
#include <cstdint>

#define BS 128
#define M_CTR 16
#define BN_SCALE 0.9999950000374997f

// ---------------- scratch ----------------
__device__ int    g_fps[BS * M_CTR];
__device__ int    g_knn[BS * M_CTR * 2];
__device__ float  g_GsT[65536 * 128];            // dense C [n=b*512+s*16+p][o]
__device__ __half g_d4h[BS * 16 * 32 * 128];     // d4 (half) [b][m][x][i]
// pre-packed fragment-order half2 weights
__device__ uint32_t g_wsp[4 * 8 * 2048];         // sparse A: [oTi][ch][2048]
__device__ uint32_t g_wdn[8 * 2048];             // dense  A: [ch][2048]
__device__ uint32_t g_wcv[12 * 2048];            // conv   A: [ch][2048]

// ---------------- helpers ----------------
__device__ __forceinline__ float gelu_exact(float x) {
    return 0.5f * x * (1.0f + erff(x * 0.70710678118654752f));
}
__device__ __forceinline__ float bn_gelu(float x, float g, float beta) {
    return gelu_exact(fmaf(g, x * BN_SCALE, beta));
}
__device__ __forceinline__ uint32_t pack_h2(float lo, float hi) {
    __half2 h = __floats2half2_rn(lo, hi);
    return *reinterpret_cast<uint32_t*>(&h);
}
__device__ __forceinline__ void mma_f16(float* d, const uint32_t* a, const uint32_t* b) {
    asm volatile(
        "mma.sync.aligned.m16n8k16.row.col.f32.f16.f16.f32 "
        "{%0,%1,%2,%3}, {%4,%5,%6,%7}, {%8,%9}, {%0,%1,%2,%3};\n"
        : "+f"(d[0]), "+f"(d[1]), "+f"(d[2]), "+f"(d[3])
        : "r"(a[0]), "r"(a[1]), "r"(a[2]), "r"(a[3]), "r"(b[0]), "r"(b[1]));
}

// ---------------------------------------------------------------------------
// Weight pack: write A-tiles in exact smem fragment order (half2).
// Inversion of the storeA mapping:
//   idx -> tile=idx>>8, ks=(idx>>7)&1, ln=(idx>>2)&31, slot=idx&3
//   r=(slot&1)*8+(ln>>2), kpl=(slot>>1)*4+(ln&3), m=tile*16+r, kp=ks*8+kpl
// ---------------------------------------------------------------------------
__global__ __launch_bounds__(256) void k_pack(const float* __restrict__ sp_w,
                                              const float* __restrict__ dn_w,
                                              const float* __restrict__ ds_w) {
    int tid = blockIdx.x * 256 + threadIdx.x;
    int sel, rem;
    if (tid < 65536)            { sel = 0; rem = tid; }
    else if (tid < 65536+16384) { sel = 1; rem = tid - 65536; }
    else if (tid < 65536+16384+24576) { sel = 2; rem = tid - 65536 - 16384; }
    else return;

    int idx = rem & 2047;
    int tile = idx >> 8, ks = (idx >> 7) & 1, ln = (idx >> 2) & 31, slot = idx & 3;
    int r = (slot & 1) * 8 + (ln >> 2);
    int kpl = (slot >> 1) * 4 + (ln & 3);
    int m = tile * 16 + r;
    int kp = ks * 8 + kpl;

    if (sel == 0) {
        int oTi = rem >> 14;
        int ch = (rem >> 11) & 7;
        int k0 = ch * 32;
        int o = oTi * 64 + (m & 63);
        size_t base = (size_t)o * 512 + ((m < 64) ? 0 : 256) + k0 + 2 * kp;
        g_wsp[rem] = pack_h2(sp_w[base], sp_w[base + 1]);
    } else if (sel == 1) {
        int ch = rem >> 11;
        int cc = ch * 16 + kp;
        g_wdn[rem] = pack_h2(dn_w[m * 256 + cc], dn_w[m * 256 + 128 + cc]);
    } else {
        int ch = rem >> 11;
        int k0 = ch * 32;
        int tap = k0 >> 7, i0 = k0 & 127;
        int i = i0 + 2 * kp;
        g_wcv[rem] = pack_h2(ds_w[m * 384 + i * 3 + tap],
                             ds_w[m * 384 + (i + 1) * 3 + tap]);
    }
}

// ---------------------------------------------------------------------------
// FPS + kNN + coor_out.  One warp per batch. (exact f32, matches reference)
// ---------------------------------------------------------------------------
__global__ __launch_bounds__(32) void k_fps_knn(const float* __restrict__ coor,
                                                float* __restrict__ coor_out) {
    int b = blockIdx.x;
    int t = threadIdx.x;
    __shared__ float cs[32][33];
    __shared__ float sq[32];
    __shared__ int   fpsi[M_CTR];

    for (int c = 0; c < 32; c++) cs[t][c] = coor[(b * 32 + t) * 32 + c];
    float s = 0.f;
    for (int c = 0; c < 32; c++) { float v = cs[t][c]; s += v * v; }
    sq[t] = s;
    __syncthreads();

    float dist = CUDART_INF_F;
    int far = 0;
    for (int it = 0; it < M_CTR; it++) {
        if (t == 0) fpsi[it] = far;
        float d = 0.f;
        #pragma unroll
        for (int c = 0; c < 32; c++) { float df = cs[t][c] - cs[far][c]; d += df * df; }
        dist = fminf(dist, d);
        float bv = dist; int bi = t;
        #pragma unroll
        for (int o = 16; o > 0; o >>= 1) {
            float ov = __shfl_xor_sync(0xffffffffu, bv, o);
            int   oi = __shfl_xor_sync(0xffffffffu, bi, o);
            if (ov > bv || (ov == bv && oi < bi)) { bv = ov; bi = oi; }
        }
        far = bi;
    }
    __syncthreads();

    for (int m = 0; m < M_CTR; m++) {
        int r = fpsi[m];
        coor_out[(b * M_CTR + m) * 32 + t] = cs[r][t];
    }
    for (int m = 0; m < M_CTR; m++) {
        int ctr = fpsi[m];
        float dot = 0.f;
        #pragma unroll
        for (int c = 0; c < 32; c++) dot += cs[ctr][c] * cs[t][c];
        float d = sq[ctr] + sq[t] - 2.0f * dot;
        float bv = d; int bi = t;
        #pragma unroll
        for (int o = 16; o > 0; o >>= 1) {
            float ov = __shfl_xor_sync(0xffffffffu, bv, o);
            int   oi = __shfl_xor_sync(0xffffffffu, bi, o);
            if (ov < bv || (ov == bv && oi < bi)) { bv = ov; bi = oi; }
        }
        int i1 = bi;
        float d2 = (t == i1) ? CUDART_INF_F : d;
        float cv = d2; int ci = t;
        #pragma unroll
        for (int o = 16; o > 0; o >>= 1) {
            float ov = __shfl_xor_sync(0xffffffffu, cv, o);
            int   oi = __shfl_xor_sync(0xffffffffu, ci, o);
            if (ov < cv || (ov == cv && oi < ci)) { cv = ov; ci = oi; }
        }
        if (t == 0) {
            g_knn[(b * M_CTR + m) * 2 + 0] = i1;
            g_knn[(b * M_CTR + m) * 2 + 1] = ci;
        }
    }
    if (t < M_CTR) g_fps[b * M_CTR + t] = fpsi[t];
}

// ---------------------------------------------------------------------------
// FAT kernel: blocks [0,256) = sparse GEMM+epilogue; [256,768) = dense GEMM.
// A-tiles streamed from pre-packed g_wsp/g_wdn (coalesced uint4 copies).
// ---------------------------------------------------------------------------
__global__ __launch_bounds__(256, 2) void fat_gemm(
        const float* __restrict__ sparse_fea,
        const float* __restrict__ sp_b, const float* __restrict__ sp_g,
        const float* __restrict__ sp_beta, float* __restrict__ out_sparse,
        const float* __restrict__ dense_fea) {
    extern __shared__ uint32_t dsm[];

    const int t = threadIdx.x;
    const int lane = t & 31;
    const int wid = t >> 5;
    const int g = lane >> 2, t4 = lane & 3;

    if (blockIdx.x < 256) {
        // =================== SPARSE PATH (128x64 tile) =====================
        uint32_t* SA = dsm;            // [2][2048]
        uint32_t* SB = dsm + 4096;     // [2][1024]
        float*    Cs = reinterpret_cast<float*>(dsm);   // [128][65]

        const int wm = wid & 3, wn = wid >> 2;
        int b0 = (blockIdx.x & 63) * 2;
        int oTi = blockIdx.x >> 6;
        int oT = oTi * 64;
        const uint32_t* Wpk = g_wsp + oTi * (8 * 2048);

        uint4 va0, va1;
        float rb[8];

        auto loadA = [&](int ch) {
            const uint4* src = reinterpret_cast<const uint4*>(Wpk + ch * 2048) + t * 2;
            va0 = src[0]; va1 = src[1];
        };
        auto loadB = [&](int ch) {
            int k0 = ch * 32;
            #pragma unroll
            for (int j = 0; j < 4; j++) {
                int idx = j * 256 + t;
                int n = idx & 63, kp = idx >> 6;
                int b = b0 + (n >> 5), s = n & 31;
                rb[2 * j]     = __ldg(&sparse_fea[((size_t)b * 256 + k0 + 2 * kp) * 32 + s]);
                rb[2 * j + 1] = __ldg(&sparse_fea[((size_t)b * 256 + k0 + 2 * kp + 1) * 32 + s]);
            }
        };
        auto storeA = [&](int buf) {
            uint4* dst = reinterpret_cast<uint4*>(SA + buf * 2048) + t * 2;
            dst[0] = va0; dst[1] = va1;
        };
        auto storeB = [&](int buf) {
            #pragma unroll
            for (int j = 0; j < 4; j++) {
                int idx = j * 256 + t;
                int n = idx & 63, kp = idx >> 6;
                int ks = kp >> 3, kpl = kp & 7;
                int ntile = n >> 3;
                int ln = (n & 7) * 4 + (kpl & 3);
                int slot = kpl >> 2;
                SB[buf * 1024 + ((ntile * 2 + ks) << 6) + (ln << 1) + slot] =
                    pack_h2(rb[2 * j], rb[2 * j + 1]);
            }
        };

        float d[2][4][4];
        #pragma unroll
        for (int mt = 0; mt < 2; mt++)
            #pragma unroll
            for (int nt = 0; nt < 4; nt++)
                #pragma unroll
                for (int e = 0; e < 4; e++) d[mt][nt][e] = 0.f;

        loadA(0); loadB(0);
        storeA(0); storeB(0);
        __syncthreads();

        for (int ch = 0; ch < 8; ch++) {
            int buf = ch & 1;
            if (ch + 1 < 8) { loadA(ch + 1); loadB(ch + 1); }
            const uint4* Af = reinterpret_cast<const uint4*>(SA + buf * 2048);
            const uint2* Bf = reinterpret_cast<const uint2*>(SB + buf * 1024);
            #pragma unroll
            for (int ks = 0; ks < 2; ks++) {
                uint32_t a[2][4], bfr[4][2];
                #pragma unroll
                for (int mt = 0; mt < 2; mt++) {
                    uint4 av = Af[((2 * wm + mt) * 2 + ks) * 32 + lane];
                    a[mt][0] = av.x; a[mt][1] = av.y; a[mt][2] = av.z; a[mt][3] = av.w;
                }
                #pragma unroll
                for (int nt = 0; nt < 4; nt++) {
                    uint2 bv = Bf[((wn * 4 + nt) * 2 + ks) * 32 + lane];
                    bfr[nt][0] = bv.x; bfr[nt][1] = bv.y;
                }
                #pragma unroll
                for (int mt = 0; mt < 2; mt++)
                    #pragma unroll
                    for (int nt = 0; nt < 4; nt++)
                        mma_f16(d[mt][nt], a[mt], bfr[nt]);
            }
            if (ch + 1 < 8) { storeA(1 - buf); storeB(1 - buf); }
            __syncthreads();
        }

        #pragma unroll
        for (int mt = 0; mt < 2; mt++)
            #pragma unroll
            for (int nt = 0; nt < 4; nt++)
                #pragma unroll
                for (int e = 0; e < 4; e++) {
                    int m = wm * 32 + mt * 16 + g + ((e & 2) ? 8 : 0);
                    int n = wn * 32 + nt * 8 + 2 * t4 + (e & 1);
                    Cs[m * 65 + n] = d[mt][nt][e];
                }
        __syncthreads();
        #pragma unroll
        for (int j = 0; j < 8; j++) {
            int idx = j * 256 + t;
            int mm = idx & 15;
            int o_loc = (idx >> 4) & 63;
            int bl = idx >> 10;
            int b = b0 + bl;
            int cb = bl * 32;
            int ctr = g_fps[b * M_CTR + mm];
            int i0 = g_knn[(b * M_CTR + mm) * 2 + 0];
            int i1 = g_knn[(b * M_CTR + mm) * 2 + 1];
            float Ha_c = Cs[o_loc * 65 + cb + ctr];
            float Hc_c = Cs[(64 + o_loc) * 65 + cb + ctr];
            float Ha0  = Cs[o_loc * 65 + cb + i0];
            float Ha1  = Cs[o_loc * 65 + cb + i1];
            int o = oT + o_loc;
            float base = -Ha_c + Hc_c + sp_b[o];
            float gg = sp_g[o], bt = sp_beta[o];
            float r = fmaxf(bn_gelu(Ha0 + base, gg, bt), bn_gelu(Ha1 + base, gg, bt));
            out_sparse[(size_t)b * 4096 + o * 16 + mm] = r;
        }
    } else {
        // =================== DENSE PATH (128x128 tile) =====================
        uint32_t* Abuf = dsm;          // [2][2048]
        uint32_t* Bbuf = dsm + 4096;   // [2][2048]
        float*    Cs   = reinterpret_cast<float*>(dsm);   // [n][132]

        const int wm = wid & 1, wn = wid >> 1;
        int dx = blockIdx.x - 256;
        int bb = dx >> 2, sg = dx & 3, s0 = sg * 8;

        uint4 va0, va1;
        uint32_t rbp[8];

        auto loadA = [&](int ch) {
            const uint4* src = reinterpret_cast<const uint4*>(g_wdn + ch * 2048) + t * 2;
            va0 = src[0]; va1 = src[1];
        };
        auto loadB = [&](int ch) {
            int k0 = ch * 32;
            #pragma unroll
            for (int j = 0; j < 8; j++) {
                int idx = j * 256 + t;
                int n = idx & 127, kp = idx >> 7;
                int c = (k0 >> 1) + kp;
                int s = s0 + (n >> 4), p = n & 15;
                float2 v = *reinterpret_cast<const float2*>(
                    &dense_fea[(((size_t)bb * 128 + c) * 32 + s) * 32 + 2 * p]);
                rbp[j] = pack_h2(v.x, v.y);
            }
        };
        auto storeA = [&](int buf) {
            uint4* dst = reinterpret_cast<uint4*>(Abuf + buf * 2048) + t * 2;
            dst[0] = va0; dst[1] = va1;
        };
        auto storeB = [&](int buf) {
            #pragma unroll
            for (int j = 0; j < 8; j++) {
                int idx = j * 256 + t;
                int n = idx & 127, kp = idx >> 7;
                int ks = kp >> 3, kpl = kp & 7;
                int ntile = n >> 3;
                int ln = (n & 7) * 4 + (kpl & 3);
                int slot = kpl >> 2;
                Bbuf[buf * 2048 + ((ntile * 2 + ks) << 6) + (ln << 1) + slot] = rbp[j];
            }
        };

        float d[4][4][4];
        #pragma unroll
        for (int mt = 0; mt < 4; mt++)
            #pragma unroll
            for (int nt = 0; nt < 4; nt++)
                #pragma unroll
                for (int e = 0; e < 4; e++) d[mt][nt][e] = 0.f;

        loadA(0); loadB(0);
        storeA(0); storeB(0);
        __syncthreads();

        for (int ch = 0; ch < 8; ch++) {
            int buf = ch & 1;
            if (ch + 1 < 8) { loadA(ch + 1); loadB(ch + 1); }
            const uint4* Af = reinterpret_cast<const uint4*>(Abuf + buf * 2048);
            const uint2* Bf = reinterpret_cast<const uint2*>(Bbuf + buf * 2048);
            #pragma unroll
            for (int ks = 0; ks < 2; ks++) {
                uint32_t a[4][4], bfr[4][2];
                #pragma unroll
                for (int mt = 0; mt < 4; mt++) {
                    uint4 av = Af[((wm * 4 + mt) * 2 + ks) * 32 + lane];
                    a[mt][0] = av.x; a[mt][1] = av.y; a[mt][2] = av.z; a[mt][3] = av.w;
                }
                #pragma unroll
                for (int nt = 0; nt < 4; nt++) {
                    uint2 bv = Bf[((wn * 4 + nt) * 2 + ks) * 32 + lane];
                    bfr[nt][0] = bv.x; bfr[nt][1] = bv.y;
                }
                #pragma unroll
                for (int mt = 0; mt < 4; mt++)
                    #pragma unroll
                    for (int nt = 0; nt < 4; nt++)
                        mma_f16(d[mt][nt], a[mt], bfr[nt]);
            }
            if (ch + 1 < 8) { storeA(1 - buf); storeB(1 - buf); }
            __syncthreads();
        }

        // transpose through smem: Cs[n][m] stride 132 -> float4 stores
        #pragma unroll
        for (int mt = 0; mt < 4; mt++)
            #pragma unroll
            for (int nt = 0; nt < 4; nt++)
                #pragma unroll
                for (int e = 0; e < 4; e++) {
                    int m = wm * 64 + mt * 16 + g + ((e & 2) ? 8 : 0);
                    int n = wn * 32 + nt * 8 + 2 * t4 + (e & 1);
                    Cs[n * 132 + m] = d[mt][nt][e];
                }
        __syncthreads();
        #pragma unroll
        for (int j = 0; j < 16; j++) {
            int idx = j * 256 + t;
            int o4 = (idx & 31) * 4, n = idx >> 5;
            float4 v = *reinterpret_cast<const float4*>(&Cs[n * 132 + o4]);
            *reinterpret_cast<float4*>(
                &g_GsT[((size_t)bb * 512 + sg * 128 + n) * 128 + o4]) = v;
        }
    }
}

// ---------------------------------------------------------------------------
// d4 paired-p, writes HALF (pre-packed for conv B-fill)
// ---------------------------------------------------------------------------
__global__ __launch_bounds__(256) void k_d4(const float* __restrict__ dn_b,
                                            const float* __restrict__ dn_g,
                                            const float* __restrict__ dn_beta) {
    int tid = blockIdx.x * 256 + threadIdx.x;
    int i = (tid & 31) * 4;
    int p = (tid >> 5) & 15;
    int m = (tid >> 9) & 15;
    int b = tid >> 13;
    int ctr = g_fps[b * M_CTR + m];
    int i0 = g_knn[(b * M_CTR + m) * 2 + 0];
    int i1 = g_knn[(b * M_CTR + m) * 2 + 1];
    float4 bb = *reinterpret_cast<const float4*>(&dn_b[i]);
    float4 gg = *reinterpret_cast<const float4*>(&dn_g[i]);
    float4 bt = *reinterpret_cast<const float4*>(&dn_beta[i]);
    const float* Gb = g_GsT + (size_t)b * 512 * 128;
    float4 gc = *reinterpret_cast<const float4*>(&Gb[(size_t)(ctr * 16 + p) * 128 + i]);
    float4 x0 = *reinterpret_cast<const float4*>(&Gb[(size_t)(i0 * 16 + p) * 128 + i]);
    float4 x1 = *reinterpret_cast<const float4*>(&Gb[(size_t)(i1 * 16 + p) * 128 + i]);
    float4 va, vb2;
    va.x = fmaxf(bn_gelu(x0.x - gc.x + bb.x, gg.x, bt.x), bn_gelu(x1.x - gc.x + bb.x, gg.x, bt.x));
    va.y = fmaxf(bn_gelu(x0.y - gc.y + bb.y, gg.y, bt.y), bn_gelu(x1.y - gc.y + bb.y, gg.y, bt.y));
    va.z = fmaxf(bn_gelu(x0.z - gc.z + bb.z, gg.z, bt.z), bn_gelu(x1.z - gc.z + bb.z, gg.z, bt.z));
    va.w = fmaxf(bn_gelu(x0.w - gc.w + bb.w, gg.w, bt.w), bn_gelu(x1.w - gc.w + bb.w, gg.w, bt.w));
    vb2.x = bn_gelu(gc.x + bb.x, gg.x, bt.x);
    vb2.y = bn_gelu(gc.y + bb.y, gg.y, bt.y);
    vb2.z = bn_gelu(gc.z + bb.z, gg.z, bt.z);
    vb2.w = bn_gelu(gc.w + bb.w, gg.w, bt.w);
    __half* outp = g_d4h + (((size_t)b * 16 + m) * 32 + p) * 128 + i;
    uint2 pa = make_uint2(pack_h2(va.x, va.y), pack_h2(va.z, va.w));
    uint2 pb = make_uint2(pack_h2(vb2.x, vb2.y), pack_h2(vb2.z, vb2.w));
    *reinterpret_cast<uint2*>(outp) = pa;
    *reinterpret_cast<uint2*>(outp + 16 * 128) = pb;
}

// ---------------------------------------------------------------------------
// Conv GEMM (R12 geometry: 128x128 tile, 8 warps 2Mx4N, KC=32, NCH=12),
// A from pre-packed g_wcv, B coalesced kq-major uint2 from g_d4h.
// ---------------------------------------------------------------------------
__global__ __launch_bounds__(256, 2) void gemm_conv(const float* __restrict__ eb,
                                                    const float* __restrict__ eg,
                                                    const float* __restrict__ ebt,
                                                    float* __restrict__ Cout) {
    extern __shared__ uint32_t dsm[];
    uint32_t* Abuf = dsm;          // [2][2048]
    uint32_t* Bbuf = dsm + 4096;   // [2][2048]

    const int t = threadIdx.x;
    const int lane = t & 31;
    const int wid = t >> 5;
    const int g = lane >> 2, t4 = lane & 3;
    const int wm = wid & 1, wn = wid >> 1;

    int bb = blockIdx.x >> 1, ng = blockIdx.x & 1;

    const int NCH = 12;
    uint4 va0, va1;
    uint32_t rbp[8];

    auto loadA = [&](int ch) {
        const uint4* src = reinterpret_cast<const uint4*>(g_wcv + ch * 2048) + t * 2;
        va0 = src[0]; va1 = src[1];
    };
    auto loadB = [&](int ch) {
        int k0 = ch * 32;
        int tap = k0 >> 7, i0 = k0 & 127;
        #pragma unroll
        for (int j = 0; j < 4; j++) {
            int idx = j * 256 + t;            // 0..1023
            int kq = idx & 7;                 // kp pair: 2*kq, 2*kq+1
            int n = (idx >> 3) & 127;
            int i = i0 + 4 * kq;
            int m = ng * 8 + (n >> 4), w = n & 15;
            int x = 2 * w - 1 + tap;
            uint2 v = (x >= 0 && x < 32)
                ? *reinterpret_cast<const uint2*>(
                      &g_d4h[(((size_t)bb * 16 + m) * 32 + x) * 128 + i])
                : make_uint2(0u, 0u);
            rbp[2 * j]     = v.x;
            rbp[2 * j + 1] = v.y;
        }
    };
    auto storeA = [&](int buf) {
        uint4* dst = reinterpret_cast<uint4*>(Abuf + buf * 2048) + t * 2;
        dst[0] = va0; dst[1] = va1;
    };
    auto storeB = [&](int buf) {
        #pragma unroll
        for (int j = 0; j < 4; j++) {
            int idx = j * 256 + t;
            int kq = idx & 7;
            int n = (idx >> 3) & 127;
            #pragma unroll
            for (int h = 0; h < 2; h++) {
                int kp = 2 * kq + h;
                int ks = kp >> 3, kpl = kp & 7;
                int ntile = n >> 3;
                int ln = (n & 7) * 4 + (kpl & 3);
                int slot = kpl >> 2;
                Bbuf[buf * 2048 + ((ntile * 2 + ks) << 6) + (ln << 1) + slot] =
                    rbp[2 * j + h];
            }
        }
    };

    float d[4][4][4];
    #pragma unroll
    for (int mt = 0; mt < 4; mt++)
        #pragma unroll
        for (int nt = 0; nt < 4; nt++)
            #pragma unroll
            for (int e = 0; e < 4; e++) d[mt][nt][e] = 0.f;

    loadA(0); loadB(0);
    storeA(0); storeB(0);
    __syncthreads();

    for (int ch = 0; ch < NCH; ch++) {
        int buf = ch & 1;
        if (ch + 1 < NCH) { loadA(ch + 1); loadB(ch + 1); }
        const uint4* Af = reinterpret_cast<const uint4*>(Abuf + buf * 2048);
        const uint2* Bf = reinterpret_cast<const uint2*>(Bbuf + buf * 2048);
        #pragma unroll
        for (int ks = 0; ks < 2; ks++) {
            uint32_t a[4][4], bfr[4][2];
            #pragma unroll
            for (int mt = 0; mt < 4; mt++) {
                uint4 av = Af[((wm * 4 + mt) * 2 + ks) * 32 + lane];
                a[mt][0] = av.x; a[mt][1] = av.y; a[mt][2] = av.z; a[mt][3] = av.w;
            }
            #pragma unroll
            for (int nt = 0; nt < 4; nt++) {
                uint2 bv = Bf[((wn * 4 + nt) * 2 + ks) * 32 + lane];
                bfr[nt][0] = bv.x; bfr[nt][1] = bv.y;
            }
            #pragma unroll
            for (int mt = 0; mt < 4; mt++)
                #pragma unroll
                for (int nt = 0; nt < 4; nt++)
                    mma_f16(d[mt][nt], a[mt], bfr[nt]);
        }
        if (ch + 1 < NCH) { storeA(1 - buf); storeB(1 - buf); }
        __syncthreads();
    }

    #pragma unroll
    for (int mt = 0; mt < 4; mt++) {
        int o_lo = wm * 64 + mt * 16 + g;
        int o_hi = o_lo + 8;
        float b_lo = eb[o_lo], g_lo = eg[o_lo], t_lo = ebt[o_lo];
        float b_hi = eb[o_hi], g_hi = eg[o_hi], t_hi = ebt[o_hi];
        #pragma unroll
        for (int nt = 0; nt < 4; nt++) {
            int n = ng * 128 + wn * 32 + nt * 8 + 2 * t4;
            float2 v0, v1;
            v0.x = bn_gelu(d[mt][nt][0] + b_lo, g_lo, t_lo);
            v0.y = bn_gelu(d[mt][nt][1] + b_lo, g_lo, t_lo);
            v1.x = bn_gelu(d[mt][nt][2] + b_hi, g_hi, t_hi);
            v1.y = bn_gelu(d[mt][nt][3] + b_hi, g_hi, t_hi);
            *reinterpret_cast<float2*>(&Cout[((size_t)bb * 128 + o_lo) * 256 + n]) = v0;
            *reinterpret_cast<float2*>(&Cout[((size_t)bb * 128 + o_hi) * 256 + n]) = v1;
        }
    }
}

// ---------------------------------------------------------------------------
extern "C" void kernel_launch(void* const* d_in, const int* in_sizes, int n_in,
                              void* d_out, int out_size) {
    const float* sparse_fea = (const float*)d_in[0];
    const float* dense_fea  = (const float*)d_in[1];
    const float* stk_coor   = (const float*)d_in[2];
    int base = 3;
    if (n_in >= 16 && in_sizes[3] == 1) base = 4;
    const float* sp_w    = (const float*)d_in[base + 0];
    const float* sp_b    = (const float*)d_in[base + 1];
    const float* sp_g    = (const float*)d_in[base + 2];
    const float* sp_beta = (const float*)d_in[base + 3];
    const float* dn_w    = (const float*)d_in[base + 4];
    const float* dn_b    = (const float*)d_in[base + 5];
    const float* dn_g    = (const float*)d_in[base + 6];
    const float* dn_beta = (const float*)d_in[base + 7];
    const float* ds_w    = (const float*)d_in[base + 8];
    const float* ds_b    = (const float*)d_in[base + 9];
    const float* ds_g    = (const float*)d_in[base + 10];
    const float* ds_beta = (const float*)d_in[base + 11];

    float* out = (float*)d_out;
    float* out_sparse = out;
    float* out_dense  = out + BS * 256 * M_CTR;
    float* out_coor   = out_dense + BS * 128 * M_CTR * 16;

    static bool attr_done = false;
    if (!attr_done) {
        cudaFuncSetAttribute(fat_gemm, cudaFuncAttributeMaxDynamicSharedMemorySize, 69632);
        cudaFuncSetAttribute(gemm_conv, cudaFuncAttributeMaxDynamicSharedMemorySize, 69632);
        attr_done = true;
    }

    k_pack<<<416, 256>>>(sp_w, dn_w, ds_w);
    k_fps_knn<<<BS, 32>>>(stk_coor, out_coor);
    fat_gemm<<<768, 256, 67584>>>(sparse_fea, sp_b, sp_g, sp_beta, out_sparse, dense_fea);
    k_d4<<<4096, 256>>>(dn_b, dn_g, dn_beta);
    gemm_conv<<<256, 256, 32768>>>(ds_b, ds_g, ds_beta, out_dense);
}

// round 15
// speedup vs baseline: 1.2573x; 1.0618x over previous
#include <cuda_runtime.h>
#include <cuda_fp16.h>
#include <math_constants.h>
#include <cstdint>

#define BS 128
#define M_CTR 16
#define BN_SCALE 0.9999950000374997f

// ---------------- scratch ----------------
__device__ int    g_fps[BS * M_CTR];
__device__ int    g_knn[BS * M_CTR * 2];
__device__ float  g_GsT[65536 * 128];            // dense C [n=b*512+s*16+p][o]
__device__ __half g_d4h[BS * 16 * 32 * 128];     // d4 (half) [b][m][x][i]
// pre-packed fragment-order half2 weights
__device__ uint32_t g_wsp[4 * 8 * 2048];         // sparse A: [oTi][ch][2048]
__device__ uint32_t g_wdn[8 * 2048];             // dense  A: [ch][2048]
__device__ uint32_t g_wcv[12 * 2048];            // conv   A: [ch][2048]

// ---------------- helpers ----------------
__device__ __forceinline__ float gelu_exact(float x) {
    return 0.5f * x * (1.0f + erff(x * 0.70710678118654752f));
}
__device__ __forceinline__ float bn_gelu(float x, float g, float beta) {
    return gelu_exact(fmaf(g, x * BN_SCALE, beta));
}
__device__ __forceinline__ float bn_gelu_pre(float x, float gs, float beta) {
    return gelu_exact(fmaf(gs, x, beta));   // gs = g * BN_SCALE (pre-multiplied)
}
__device__ __forceinline__ uint32_t pack_h2(float lo, float hi) {
    __half2 h = __floats2half2_rn(lo, hi);
    return *reinterpret_cast<uint32_t*>(&h);
}
__device__ __forceinline__ void mma_f16(float* d, const uint32_t* a, const uint32_t* b) {
    asm volatile(
        "mma.sync.aligned.m16n8k16.row.col.f32.f16.f16.f32 "
        "{%0,%1,%2,%3}, {%4,%5,%6,%7}, {%8,%9}, {%0,%1,%2,%3};\n"
        : "+f"(d[0]), "+f"(d[1]), "+f"(d[2]), "+f"(d[3])
        : "r"(a[0]), "r"(a[1]), "r"(a[2]), "r"(a[3]), "r"(b[0]), "r"(b[1]));
}

// ---------------------------------------------------------------------------
// PRE kernel: blocks [0,416) = weight pack; blocks [416,544) = FPS+kNN.
// ---------------------------------------------------------------------------
__global__ __launch_bounds__(256) void k_pre(const float* __restrict__ sp_w,
                                             const float* __restrict__ dn_w,
                                             const float* __restrict__ ds_w,
                                             const float* __restrict__ coor,
                                             float* __restrict__ coor_out) {
    if (blockIdx.x < 416) {
        int tid = blockIdx.x * 256 + threadIdx.x;
        int sel, rem;
        if (tid < 65536)                  { sel = 0; rem = tid; }
        else if (tid < 65536 + 16384)     { sel = 1; rem = tid - 65536; }
        else                              { sel = 2; rem = tid - 65536 - 16384; }

        int idx = rem & 2047;
        int tile = idx >> 8, ks = (idx >> 7) & 1, ln = (idx >> 2) & 31, slot = idx & 3;
        int r = (slot & 1) * 8 + (ln >> 2);
        int kpl = (slot >> 1) * 4 + (ln & 3);
        int m = tile * 16 + r;
        int kp = ks * 8 + kpl;

        if (sel == 0) {
            int oTi = rem >> 14;
            int ch = (rem >> 11) & 7;
            int k0 = ch * 32;
            int o = oTi * 64 + (m & 63);
            size_t base = (size_t)o * 512 + ((m < 64) ? 0 : 256) + k0 + 2 * kp;
            g_wsp[rem] = pack_h2(sp_w[base], sp_w[base + 1]);
        } else if (sel == 1) {
            int ch = rem >> 11;
            int cc = ch * 16 + kp;
            g_wdn[rem] = pack_h2(dn_w[m * 256 + cc], dn_w[m * 256 + 128 + cc]);
        } else {
            int ch = rem >> 11;
            int k0 = ch * 32;
            int tap = k0 >> 7, i0 = k0 & 127;
            int i = i0 + 2 * kp;
            g_wcv[rem] = pack_h2(ds_w[m * 384 + i * 3 + tap],
                                 ds_w[m * 384 + (i + 1) * 3 + tap]);
        }
        return;
    }

    // ---------------- FPS + kNN (warp 0 active; exact f32) ----------------
    int b = blockIdx.x - 416;
    int t = threadIdx.x;
    bool act = (t < 32);
    __shared__ float cs[32][33];
    __shared__ float sq[32];
    __shared__ int   fpsi[M_CTR];
    __shared__ int   knn_s[M_CTR][2];
    __shared__ int   farv;

    if (act) {
        for (int c = 0; c < 32; c++) cs[t][c] = coor[(b * 32 + t) * 32 + c];
        float s = 0.f;
        for (int c = 0; c < 32; c++) { float v = cs[t][c]; s += v * v; }
        sq[t] = s;
    }
    __syncthreads();

    if (act) {
        float dist = CUDART_INF_F;
        int far = 0;
        for (int it = 0; it < M_CTR; it++) {
            if (t == 0) fpsi[it] = far;
            float d = 0.f;
            #pragma unroll
            for (int c = 0; c < 32; c++) { float df = cs[t][c] - cs[far][c]; d += df * df; }
            dist = fminf(dist, d);
            float bv = dist; int bi = t;
            #pragma unroll
            for (int o = 16; o > 0; o >>= 1) {
                float ov = __shfl_xor_sync(0xffffffffu, bv, o);
                int   oi = __shfl_xor_sync(0xffffffffu, bi, o);
                if (ov > bv || (ov == bv && oi < bi)) { bv = ov; bi = oi; }
            }
            far = bi;
        }
        (void)farv;
        for (int m = 0; m < M_CTR; m++) {
            int rr = fpsi[m];
            coor_out[(b * M_CTR + m) * 32 + t] = cs[rr][t];
        }
        for (int m = 0; m < M_CTR; m++) {
            int ctr = fpsi[m];
            float dot = 0.f;
            #pragma unroll
            for (int c = 0; c < 32; c++) dot += cs[ctr][c] * cs[t][c];
            float d = sq[ctr] + sq[t] - 2.0f * dot;
            float bv = d; int bi = t;
            #pragma unroll
            for (int o = 16; o > 0; o >>= 1) {
                float ov = __shfl_xor_sync(0xffffffffu, bv, o);
                int   oi = __shfl_xor_sync(0xffffffffu, bi, o);
                if (ov < bv || (ov == bv && oi < bi)) { bv = ov; bi = oi; }
            }
            int i1 = bi;
            float d2 = (t == i1) ? CUDART_INF_F : d;
            float cv = d2; int ci = t;
            #pragma unroll
            for (int o = 16; o > 0; o >>= 1) {
                float ov = __shfl_xor_sync(0xffffffffu, cv, o);
                int   oi = __shfl_xor_sync(0xffffffffu, ci, o);
                if (ov < cv || (ov == cv && oi < ci)) { cv = ov; ci = oi; }
            }
            if (t == 0) { knn_s[m][0] = i1; knn_s[m][1] = ci; }
        }
        if (t == 0) {
            for (int m = 0; m < M_CTR; m++) {
                g_knn[(b * M_CTR + m) * 2 + 0] = knn_s[m][0];
                g_knn[(b * M_CTR + m) * 2 + 1] = knn_s[m][1];
            }
        }
        if (t < M_CTR) g_fps[b * M_CTR + t] = fpsi[t];
    }
}

// ---------------------------------------------------------------------------
// FAT kernel: blocks [0,512) = dense GEMM (long pole, starts first);
//             blocks [512,768) = sparse GEMM+epilogue.
// ---------------------------------------------------------------------------
__global__ __launch_bounds__(256, 2) void fat_gemm(
        const float* __restrict__ sparse_fea,
        const float* __restrict__ sp_b, const float* __restrict__ sp_g,
        const float* __restrict__ sp_beta, float* __restrict__ out_sparse,
        const float* __restrict__ dense_fea) {
    extern __shared__ uint32_t dsm[];

    const int t = threadIdx.x;
    const int lane = t & 31;
    const int wid = t >> 5;
    const int g = lane >> 2, t4 = lane & 3;

    if (blockIdx.x < 512) {
        // =================== DENSE PATH (128x128 tile) =====================
        uint32_t* Abuf = dsm;          // [2][2048]
        uint32_t* Bbuf = dsm + 4096;   // [2][2048]
        float*    Cs   = reinterpret_cast<float*>(dsm);   // [n][132]

        const int wm = wid & 1, wn = wid >> 1;
        int dx = blockIdx.x;
        int bb = dx >> 2, sg = dx & 3, s0 = sg * 8;

        uint4 va0, va1;
        uint32_t rbp[8];

        auto loadA = [&](int ch) {
            const uint4* src = reinterpret_cast<const uint4*>(g_wdn + ch * 2048) + t * 2;
            va0 = src[0]; va1 = src[1];
        };
        auto loadB = [&](int ch) {
            int k0 = ch * 32;
            #pragma unroll
            for (int j = 0; j < 8; j++) {
                int idx = j * 256 + t;
                int n = idx & 127, kp = idx >> 7;
                int c = (k0 >> 1) + kp;
                int s = s0 + (n >> 4), p = n & 15;
                float2 v = *reinterpret_cast<const float2*>(
                    &dense_fea[(((size_t)bb * 128 + c) * 32 + s) * 32 + 2 * p]);
                rbp[j] = pack_h2(v.x, v.y);
            }
        };
        auto storeA = [&](int buf) {
            uint4* dst = reinterpret_cast<uint4*>(Abuf + buf * 2048) + t * 2;
            dst[0] = va0; dst[1] = va1;
        };
        auto storeB = [&](int buf) {
            #pragma unroll
            for (int j = 0; j < 8; j++) {
                int idx = j * 256 + t;
                int n = idx & 127, kp = idx >> 7;
                int ks = kp >> 3, kpl = kp & 7;
                int ntile = n >> 3;
                int ln = (n & 7) * 4 + (kpl & 3);
                int slot = kpl >> 2;
                Bbuf[buf * 2048 + ((ntile * 2 + ks) << 6) + (ln << 1) + slot] = rbp[j];
            }
        };

        float d[4][4][4];
        #pragma unroll
        for (int mt = 0; mt < 4; mt++)
            #pragma unroll
            for (int nt = 0; nt < 4; nt++)
                #pragma unroll
                for (int e = 0; e < 4; e++) d[mt][nt][e] = 0.f;

        loadA(0); loadB(0);
        storeA(0); storeB(0);
        __syncthreads();

        for (int ch = 0; ch < 8; ch++) {
            int buf = ch & 1;
            if (ch + 1 < 8) { loadA(ch + 1); loadB(ch + 1); }
            const uint4* Af = reinterpret_cast<const uint4*>(Abuf + buf * 2048);
            const uint2* Bf = reinterpret_cast<const uint2*>(Bbuf + buf * 2048);
            #pragma unroll
            for (int ks = 0; ks < 2; ks++) {
                uint32_t a[4][4], bfr[4][2];
                #pragma unroll
                for (int mt = 0; mt < 4; mt++) {
                    uint4 av = Af[((wm * 4 + mt) * 2 + ks) * 32 + lane];
                    a[mt][0] = av.x; a[mt][1] = av.y; a[mt][2] = av.z; a[mt][3] = av.w;
                }
                #pragma unroll
                for (int nt = 0; nt < 4; nt++) {
                    uint2 bv = Bf[((wn * 4 + nt) * 2 + ks) * 32 + lane];
                    bfr[nt][0] = bv.x; bfr[nt][1] = bv.y;
                }
                #pragma unroll
                for (int mt = 0; mt < 4; mt++)
                    #pragma unroll
                    for (int nt = 0; nt < 4; nt++)
                        mma_f16(d[mt][nt], a[mt], bfr[nt]);
            }
            if (ch + 1 < 8) { storeA(1 - buf); storeB(1 - buf); }
            __syncthreads();
        }

        #pragma unroll
        for (int mt = 0; mt < 4; mt++)
            #pragma unroll
            for (int nt = 0; nt < 4; nt++)
                #pragma unroll
                for (int e = 0; e < 4; e++) {
                    int m = wm * 64 + mt * 16 + g + ((e & 2) ? 8 : 0);
                    int n = wn * 32 + nt * 8 + 2 * t4 + (e & 1);
                    Cs[n * 132 + m] = d[mt][nt][e];
                }
        __syncthreads();
        #pragma unroll
        for (int j = 0; j < 16; j++) {
            int idx = j * 256 + t;
            int o4 = (idx & 31) * 4, n = idx >> 5;
            float4 v = *reinterpret_cast<const float4*>(&Cs[n * 132 + o4]);
            *reinterpret_cast<float4*>(
                &g_GsT[((size_t)bb * 512 + sg * 128 + n) * 128 + o4]) = v;
        }
    } else {
        // =================== SPARSE PATH (128x64 tile) =====================
        uint32_t* SA = dsm;            // [2][2048]
        uint32_t* SB = dsm + 4096;     // [2][1024]
        float*    Cs = reinterpret_cast<float*>(dsm);   // [128][65]

        const int wm = wid & 3, wn = wid >> 2;
        int sx = blockIdx.x - 512;
        int b0 = (sx & 63) * 2;
        int oTi = sx >> 6;
        int oT = oTi * 64;
        const uint32_t* Wpk = g_wsp + oTi * (8 * 2048);

        uint4 va0, va1;
        float rb[8];

        auto loadA = [&](int ch) {
            const uint4* src = reinterpret_cast<const uint4*>(Wpk + ch * 2048) + t * 2;
            va0 = src[0]; va1 = src[1];
        };
        auto loadB = [&](int ch) {
            int k0 = ch * 32;
            #pragma unroll
            for (int j = 0; j < 4; j++) {
                int idx = j * 256 + t;
                int n = idx & 63, kp = idx >> 6;
                int b = b0 + (n >> 5), s = n & 31;
                rb[2 * j]     = __ldg(&sparse_fea[((size_t)b * 256 + k0 + 2 * kp) * 32 + s]);
                rb[2 * j + 1] = __ldg(&sparse_fea[((size_t)b * 256 + k0 + 2 * kp + 1) * 32 + s]);
            }
        };
        auto storeA = [&](int buf) {
            uint4* dst = reinterpret_cast<uint4*>(SA + buf * 2048) + t * 2;
            dst[0] = va0; dst[1] = va1;
        };
        auto storeB = [&](int buf) {
            #pragma unroll
            for (int j = 0; j < 4; j++) {
                int idx = j * 256 + t;
                int n = idx & 63, kp = idx >> 6;
                int ks = kp >> 3, kpl = kp & 7;
                int ntile = n >> 3;
                int ln = (n & 7) * 4 + (kpl & 3);
                int slot = kpl >> 2;
                SB[buf * 1024 + ((ntile * 2 + ks) << 6) + (ln << 1) + slot] =
                    pack_h2(rb[2 * j], rb[2 * j + 1]);
            }
        };

        float d[2][4][4];
        #pragma unroll
        for (int mt = 0; mt < 2; mt++)
            #pragma unroll
            for (int nt = 0; nt < 4; nt++)
                #pragma unroll
                for (int e = 0; e < 4; e++) d[mt][nt][e] = 0.f;

        loadA(0); loadB(0);
        storeA(0); storeB(0);
        __syncthreads();

        for (int ch = 0; ch < 8; ch++) {
            int buf = ch & 1;
            if (ch + 1 < 8) { loadA(ch + 1); loadB(ch + 1); }
            const uint4* Af = reinterpret_cast<const uint4*>(SA + buf * 2048);
            const uint2* Bf = reinterpret_cast<const uint2*>(SB + buf * 1024);
            #pragma unroll
            for (int ks = 0; ks < 2; ks++) {
                uint32_t a[2][4], bfr[4][2];
                #pragma unroll
                for (int mt = 0; mt < 2; mt++) {
                    uint4 av = Af[((2 * wm + mt) * 2 + ks) * 32 + lane];
                    a[mt][0] = av.x; a[mt][1] = av.y; a[mt][2] = av.z; a[mt][3] = av.w;
                }
                #pragma unroll
                for (int nt = 0; nt < 4; nt++) {
                    uint2 bv = Bf[((wn * 4 + nt) * 2 + ks) * 32 + lane];
                    bfr[nt][0] = bv.x; bfr[nt][1] = bv.y;
                }
                #pragma unroll
                for (int mt = 0; mt < 2; mt++)
                    #pragma unroll
                    for (int nt = 0; nt < 4; nt++)
                        mma_f16(d[mt][nt], a[mt], bfr[nt]);
            }
            if (ch + 1 < 8) { storeA(1 - buf); storeB(1 - buf); }
            __syncthreads();
        }

        #pragma unroll
        for (int mt = 0; mt < 2; mt++)
            #pragma unroll
            for (int nt = 0; nt < 4; nt++)
                #pragma unroll
                for (int e = 0; e < 4; e++) {
                    int m = wm * 32 + mt * 16 + g + ((e & 2) ? 8 : 0);
                    int n = wn * 32 + nt * 8 + 2 * t4 + (e & 1);
                    Cs[m * 65 + n] = d[mt][nt][e];
                }
        __syncthreads();
        #pragma unroll
        for (int j = 0; j < 8; j++) {
            int idx = j * 256 + t;
            int mm = idx & 15;
            int o_loc = (idx >> 4) & 63;
            int bl = idx >> 10;
            int b = b0 + bl;
            int cb = bl * 32;
            int ctr = g_fps[b * M_CTR + mm];
            int i0 = g_knn[(b * M_CTR + mm) * 2 + 0];
            int i1 = g_knn[(b * M_CTR + mm) * 2 + 1];
            float Ha_c = Cs[o_loc * 65 + cb + ctr];
            float Hc_c = Cs[(64 + o_loc) * 65 + cb + ctr];
            float Ha0  = Cs[o_loc * 65 + cb + i0];
            float Ha1  = Cs[o_loc * 65 + cb + i1];
            int o = oT + o_loc;
            float base = -Ha_c + Hc_c + sp_b[o];
            float gg = sp_g[o], bt = sp_beta[o];
            float r = fmaxf(bn_gelu(Ha0 + base, gg, bt), bn_gelu(Ha1 + base, gg, bt));
            out_sparse[(size_t)b * 4096 + o * 16 + mm] = r;
        }
    }
}

// ---------------------------------------------------------------------------
// d4 paired-p, writes HALF; gamma pre-scaled by BN_SCALE (ALU diet)
// ---------------------------------------------------------------------------
__global__ __launch_bounds__(256) void k_d4(const float* __restrict__ dn_b,
                                            const float* __restrict__ dn_g,
                                            const float* __restrict__ dn_beta) {
    int tid = blockIdx.x * 256 + threadIdx.x;
    int i = (tid & 31) * 4;
    int p = (tid >> 5) & 15;
    int m = (tid >> 9) & 15;
    int b = tid >> 13;
    int ctr = g_fps[b * M_CTR + m];
    int i0 = g_knn[(b * M_CTR + m) * 2 + 0];
    int i1 = g_knn[(b * M_CTR + m) * 2 + 1];
    float4 bb = *reinterpret_cast<const float4*>(&dn_b[i]);
    float4 gg = *reinterpret_cast<const float4*>(&dn_g[i]);
    float4 bt = *reinterpret_cast<const float4*>(&dn_beta[i]);
    float4 gs;
    gs.x = gg.x * BN_SCALE; gs.y = gg.y * BN_SCALE;
    gs.z = gg.z * BN_SCALE; gs.w = gg.w * BN_SCALE;
    const float* Gb = g_GsT + (size_t)b * 512 * 128;
    float4 gc = *reinterpret_cast<const float4*>(&Gb[(size_t)(ctr * 16 + p) * 128 + i]);
    float4 x0 = *reinterpret_cast<const float4*>(&Gb[(size_t)(i0 * 16 + p) * 128 + i]);
    float4 x1 = *reinterpret_cast<const float4*>(&Gb[(size_t)(i1 * 16 + p) * 128 + i]);
    float4 va, vb2;
    va.x = fmaxf(bn_gelu_pre(x0.x - gc.x + bb.x, gs.x, bt.x), bn_gelu_pre(x1.x - gc.x + bb.x, gs.x, bt.x));
    va.y = fmaxf(bn_gelu_pre(x0.y - gc.y + bb.y, gs.y, bt.y), bn_gelu_pre(x1.y - gc.y + bb.y, gs.y, bt.y));
    va.z = fmaxf(bn_gelu_pre(x0.z - gc.z + bb.z, gs.z, bt.z), bn_gelu_pre(x1.z - gc.z + bb.z, gs.z, bt.z));
    va.w = fmaxf(bn_gelu_pre(x0.w - gc.w + bb.w, gs.w, bt.w), bn_gelu_pre(x1.w - gc.w + bb.w, gs.w, bt.w));
    vb2.x = bn_gelu_pre(gc.x + bb.x, gs.x, bt.x);
    vb2.y = bn_gelu_pre(gc.y + bb.y, gs.y, bt.y);
    vb2.z = bn_gelu_pre(gc.z + bb.z, gs.z, bt.z);
    vb2.w = bn_gelu_pre(gc.w + bb.w, gs.w, bt.w);
    __half* outp = g_d4h + (((size_t)b * 16 + m) * 32 + p) * 128 + i;
    uint2 pa = make_uint2(pack_h2(va.x, va.y), pack_h2(va.z, va.w));
    uint2 pb = make_uint2(pack_h2(vb2.x, vb2.y), pack_h2(vb2.z, vb2.w));
    *reinterpret_cast<uint2*>(outp) = pa;
    *reinterpret_cast<uint2*>(outp + 16 * 128) = pb;
}

// ---------------------------------------------------------------------------
// Conv GEMM (frozen R14: 128x128 tile, KC=32, NCH=12, pre-packed A,
// kq-major coalesced B from g_d4h)
// ---------------------------------------------------------------------------
__global__ __launch_bounds__(256, 2) void gemm_conv(const float* __restrict__ eb,
                                                    const float* __restrict__ eg,
                                                    const float* __restrict__ ebt,
                                                    float* __restrict__ Cout) {
    extern __shared__ uint32_t dsm[];
    uint32_t* Abuf = dsm;          // [2][2048]
    uint32_t* Bbuf = dsm + 4096;   // [2][2048]

    const int t = threadIdx.x;
    const int lane = t & 31;
    const int wid = t >> 5;
    const int g = lane >> 2, t4 = lane & 3;
    const int wm = wid & 1, wn = wid >> 1;

    int bb = blockIdx.x >> 1, ng = blockIdx.x & 1;

    const int NCH = 12;
    uint4 va0, va1;
    uint32_t rbp[8];

    auto loadA = [&](int ch) {
        const uint4* src = reinterpret_cast<const uint4*>(g_wcv + ch * 2048) + t * 2;
        va0 = src[0]; va1 = src[1];
    };
    auto loadB = [&](int ch) {
        int k0 = ch * 32;
        int tap = k0 >> 7, i0 = k0 & 127;
        #pragma unroll
        for (int j = 0; j < 4; j++) {
            int idx = j * 256 + t;
            int kq = idx & 7;
            int n = (idx >> 3) & 127;
            int i = i0 + 4 * kq;
            int m = ng * 8 + (n >> 4), w = n & 15;
            int x = 2 * w - 1 + tap;
            uint2 v = (x >= 0 && x < 32)
                ? *reinterpret_cast<const uint2*>(
                      &g_d4h[(((size_t)bb * 16 + m) * 32 + x) * 128 + i])
                : make_uint2(0u, 0u);
            rbp[2 * j]     = v.x;
            rbp[2 * j + 1] = v.y;
        }
    };
    auto storeA = [&](int buf) {
        uint4* dst = reinterpret_cast<uint4*>(Abuf + buf * 2048) + t * 2;
        dst[0] = va0; dst[1] = va1;
    };
    auto storeB = [&](int buf) {
        #pragma unroll
        for (int j = 0; j < 4; j++) {
            int idx = j * 256 + t;
            int kq = idx & 7;
            int n = (idx >> 3) & 127;
            #pragma unroll
            for (int h = 0; h < 2; h++) {
                int kp = 2 * kq + h;
                int ks = kp >> 3, kpl = kp & 7;
                int ntile = n >> 3;
                int ln = (n & 7) * 4 + (kpl & 3);
                int slot = kpl >> 2;
                Bbuf[buf * 2048 + ((ntile * 2 + ks) << 6) + (ln << 1) + slot] =
                    rbp[2 * j + h];
            }
        }
    };

    float d[4][4][4];
    #pragma unroll
    for (int mt = 0; mt < 4; mt++)
        #pragma unroll
        for (int nt = 0; nt < 4; nt++)
            #pragma unroll
            for (int e = 0; e < 4; e++) d[mt][nt][e] = 0.f;

    loadA(0); loadB(0);
    storeA(0); storeB(0);
    __syncthreads();

    for (int ch = 0; ch < NCH; ch++) {
        int buf = ch & 1;
        if (ch + 1 < NCH) { loadA(ch + 1); loadB(ch + 1); }
        const uint4* Af = reinterpret_cast<const uint4*>(Abuf + buf * 2048);
        const uint2* Bf = reinterpret_cast<const uint2*>(Bbuf + buf * 2048);
        #pragma unroll
        for (int ks = 0; ks < 2; ks++) {
            uint32_t a[4][4], bfr[4][2];
            #pragma unroll
            for (int mt = 0; mt < 4; mt++) {
                uint4 av = Af[((wm * 4 + mt) * 2 + ks) * 32 + lane];
                a[mt][0] = av.x; a[mt][1] = av.y; a[mt][2] = av.z; a[mt][3] = av.w;
            }
            #pragma unroll
            for (int nt = 0; nt < 4; nt++) {
                uint2 bv = Bf[((wn * 4 + nt) * 2 + ks) * 32 + lane];
                bfr[nt][0] = bv.x; bfr[nt][1] = bv.y;
            }
            #pragma unroll
            for (int mt = 0; mt < 4; mt++)
                #pragma unroll
                for (int nt = 0; nt < 4; nt++)
                    mma_f16(d[mt][nt], a[mt], bfr[nt]);
        }
        if (ch + 1 < NCH) { storeA(1 - buf); storeB(1 - buf); }
        __syncthreads();
    }

    #pragma unroll
    for (int mt = 0; mt < 4; mt++) {
        int o_lo = wm * 64 + mt * 16 + g;
        int o_hi = o_lo + 8;
        float b_lo = eb[o_lo], g_lo = eg[o_lo], t_lo = ebt[o_lo];
        float b_hi = eb[o_hi], g_hi = eg[o_hi], t_hi = ebt[o_hi];
        #pragma unroll
        for (int nt = 0; nt < 4; nt++) {
            int n = ng * 128 + wn * 32 + nt * 8 + 2 * t4;
            float2 v0, v1;
            v0.x = bn_gelu(d[mt][nt][0] + b_lo, g_lo, t_lo);
            v0.y = bn_gelu(d[mt][nt][1] + b_lo, g_lo, t_lo);
            v1.x = bn_gelu(d[mt][nt][2] + b_hi, g_hi, t_hi);
            v1.y = bn_gelu(d[mt][nt][3] + b_hi, g_hi, t_hi);
            *reinterpret_cast<float2*>(&Cout[((size_t)bb * 128 + o_lo) * 256 + n]) = v0;
            *reinterpret_cast<float2*>(&Cout[((size_t)bb * 128 + o_hi) * 256 + n]) = v1;
        }
    }
}

// ---------------------------------------------------------------------------
extern "C" void kernel_launch(void* const* d_in, const int* in_sizes, int n_in,
                              void* d_out, int out_size) {
    const float* sparse_fea = (const float*)d_in[0];
    const float* dense_fea  = (const float*)d_in[1];
    const float* stk_coor   = (const float*)d_in[2];
    int base = 3;
    if (n_in >= 16 && in_sizes[3] == 1) base = 4;
    const float* sp_w    = (const float*)d_in[base + 0];
    const float* sp_b    = (const float*)d_in[base + 1];
    const float* sp_g    = (const float*)d_in[base + 2];
    const float* sp_beta = (const float*)d_in[base + 3];
    const float* dn_w    = (const float*)d_in[base + 4];
    const float* dn_b    = (const float*)d_in[base + 5];
    const float* dn_g    = (const float*)d_in[base + 6];
    const float* dn_beta = (const float*)d_in[base + 7];
    const float* ds_w    = (const float*)d_in[base + 8];
    const float* ds_b    = (const float*)d_in[base + 9];
    const float* ds_g    = (const float*)d_in[base + 10];
    const float* ds_beta = (const float*)d_in[base + 11];

    float* out = (float*)d_out;
    float* out_sparse = out;
    float* out_dense  = out + BS * 256 * M_CTR;
    float* out_coor   = out_dense + BS * 128 * M_CTR * 16;

    static bool attr_done = false;
    if (!attr_done) {
        cudaFuncSetAttribute(fat_gemm, cudaFuncAttributeMaxDynamicSharedMemorySize, 69632);
        cudaFuncSetAttribute(gemm_conv, cudaFuncAttributeMaxDynamicSharedMemorySize, 69632);
        attr_done = true;
    }

    k_pre<<<544, 256>>>(sp_w, dn_w, ds_w, stk_coor, out_coor);
    fat_gemm<<<768, 256, 67584>>>(sparse_fea, sp_b, sp_g, sp_beta, out_sparse, dense_fea);
    k_d4<<<4096, 256>>>(dn_b, dn_g, dn_beta);
    gemm_conv<<<256, 256, 32768>>>(ds_b, ds_g, ds_beta, out_dense);
}